// round 1
// baseline (speedup 1.0000x reference)
#include <cuda_runtime.h>
#include <math.h>

// KernalAnsatz_65481071409588 — GB300 (sm_103a)
//
// Algebraic reduction: psi_x = C·R(x)|0>, psi_y = C·R(y)|0> with C (the
// param-dependent rotation layers + CNOT rings) IDENTICAL for both states.
// Hence <psi_x|psi_y> = <0|R(x)†R(y)|0> = prod_q cos((x_q - y_q)/2), and the
// output is prod_q cos^2((x_q - y_q)/2). Computed in fp64, emitted as fp32.
//
// N_QUBITS = 23. Inputs (metadata order): x[23] f32, y[23] f32, params[138] f32
// (params unused — they cancel exactly). Output: 1 x f32.

#define N_QUBITS 23

__global__ void KernalAnsatz_65481071409588_kernel(const float* __restrict__ x,
                                                   const float* __restrict__ y,
                                                   float* __restrict__ out) {
    const int lane = threadIdx.x;  // one warp
    double c2 = 1.0;               // lanes >= N_QUBITS contribute identity
    if (lane < N_QUBITS) {
        double d = ((double)x[lane] - (double)y[lane]) * 0.5;
        double c = cos(d);
        c2 = c * c;
    }
    // Warp-wide product reduction (all 32 lanes participate; inactive hold 1.0).
    #pragma unroll
    for (int off = 16; off > 0; off >>= 1) {
        c2 *= __shfl_down_sync(0xFFFFFFFFu, c2, off);
    }
    if (lane == 0) {
        out[0] = (float)c2;
    }
}

extern "C" void kernel_launch(void* const* d_in, const int* in_sizes, int n_in,
                              void* d_out, int out_size) {
    (void)in_sizes; (void)n_in; (void)out_size;
    const float* x = (const float*)d_in[0];
    const float* y = (const float*)d_in[1];
    // d_in[2] = params — unused: the shared circuit unitary cancels in the overlap.
    float* out = (float*)d_out;
    KernalAnsatz_65481071409588_kernel<<<1, 32>>>(x, y, out);
}

// round 2
// speedup vs baseline: 1.4211x; 1.4211x over previous
#include <cuda_runtime.h>
#include <math.h>

// KernalAnsatz_65481071409588 — GB300 (sm_103a)
//
// Algebraic reduction (see R1): the param-dependent circuit unitary C is
// identical for psi_x and psi_y, so it cancels in the overlap:
//   |<psi_x|psi_y>|^2 = prod_q cos^2((x_q - y_q)/2).
// R1 used fp64 cos (slow software DFMA chain, ~5.6us kernel). R2: fp32 cosf —
// short FFMA polynomial. Error budget: <=few ulp/factor * 23 ~ 3e-6 rel, vs
// measured reference noise 7.1e-5 and tolerance 1e-3.
//
// Inputs (metadata order): x[23] f32, y[23] f32, params[138] f32 (unused —
// cancels exactly). Output: 1 x f32.

#define N_QUBITS 23

__global__ void KernalAnsatz_65481071409588_kernel(const float* __restrict__ x,
                                                   const float* __restrict__ y,
                                                   float* __restrict__ out) {
    const int lane = threadIdx.x;  // one warp
    float c2 = 1.0f;               // lanes >= N_QUBITS contribute identity
    if (lane < N_QUBITS) {
        float d = (x[lane] - y[lane]) * 0.5f;
        float c = cosf(d);         // no cancellation: square of cos, not (1+cos)/2
        c2 = c * c;
    }
    // Warp-wide product reduction (inactive lanes hold 1.0).
    #pragma unroll
    for (int off = 16; off > 0; off >>= 1) {
        c2 *= __shfl_xor_sync(0xFFFFFFFFu, c2, off);
    }
    if (lane == 0) {
        out[0] = c2;
    }
}

extern "C" void kernel_launch(void* const* d_in, const int* in_sizes, int n_in,
                              void* d_out, int out_size) {
    (void)in_sizes; (void)n_in; (void)out_size;
    const float* x = (const float*)d_in[0];
    const float* y = (const float*)d_in[1];
    // d_in[2] = params — unused: the shared circuit unitary cancels in the overlap.
    float* out = (float*)d_out;
    KernalAnsatz_65481071409588_kernel<<<1, 32>>>(x, y, out);
}

// round 3
// speedup vs baseline: 1.5000x; 1.0556x over previous
#include <cuda_runtime.h>

// KernalAnsatz_65481071409588 — GB300 (sm_103a)
//
// Algebraic reduction (R1): the param-dependent circuit unitary C is identical
// for psi_x and psi_y and cancels in the overlap:
//   |<psi_x|psi_y>|^2 = prod_q cos^2((x_q - y_q)/2),  q = 0..22.
//
// R3: __cosf (RRO + MUFU.COS, 2 SASS instrs) replaces cosf's ~40-instr
// polynomial + slow-path branch. |d| <~ 3.5 < pi for these inputs, so
// __cosf abs err ~4e-7 -> <~2e-5 rel on the product; measured reference
// noise is 7e-5 and the gate is 1e-3. Straight-line (no divergence):
// inactive lanes compute __cosf(0) = 1.
//
// Inputs (metadata order): x[23] f32, y[23] f32, params[138] f32 (unused —
// cancels exactly). Output: 1 x f32.

#define N_QUBITS 23

__global__ void KernalAnsatz_65481071409588_kernel(const float* __restrict__ x,
                                                   const float* __restrict__ y,
                                                   float* __restrict__ out) {
    const int lane = threadIdx.x;  // one warp
    float d = 0.0f;                // lanes >= N_QUBITS: cos(0) = 1 (identity)
    if (lane < N_QUBITS) {
        d = (x[lane] - y[lane]) * 0.5f;
    }
    float c2 = __cosf(d);          // RRO.SINCOS + MUFU.COS
    c2 *= c2;
    // Warp-wide product reduction (5-level butterfly; inactive lanes hold 1.0).
    #pragma unroll
    for (int off = 16; off > 0; off >>= 1) {
        c2 *= __shfl_xor_sync(0xFFFFFFFFu, c2, off);
    }
    if (lane == 0) {
        out[0] = c2;
    }
}

extern "C" void kernel_launch(void* const* d_in, const int* in_sizes, int n_in,
                              void* d_out, int out_size) {
    (void)in_sizes; (void)n_in; (void)out_size;
    const float* x = (const float*)d_in[0];
    const float* y = (const float*)d_in[1];
    // d_in[2] = params — unused: the shared circuit unitary cancels in the overlap.
    float* out = (float*)d_out;
    KernalAnsatz_65481071409588_kernel<<<1, 32>>>(x, y, out);
}